// round 1
// baseline (speedup 1.0000x reference)
#include <cuda_runtime.h>

#define BB   32
#define CC   512
#define HW2  1024
#define NW   77
#define WD   256
#define M_WE (BB * NW)   // 2464

// Scratch: we[b][n][k], k contiguous. 32*77*1024 floats = 10.1 MB.
__device__ float g_we[BB * NW * HW2];

// ---------------------------------------------------------------------------
// Kernel 1: we[m][k] = word_emb_flat[m][:] . W_fc[k][:] + b_fc[k]
// GEMM M=2464, N=1024, K=256 (both operands K-major -> A @ B^T).
// 64x64 tile, 256 threads, each thread 4x4.
// ---------------------------------------------------------------------------
__global__ void we_gemm(const float* __restrict__ we_in,
                        const float* __restrict__ Wfc,
                        const float* __restrict__ bfc) {
    __shared__ float As[64][33];
    __shared__ float Bs[64][33];

    const int tid = threadIdx.x;
    const int tx  = tid & 15;
    const int ty  = tid >> 4;
    const int m0  = blockIdx.y * 64;
    const int k0  = blockIdx.x * 64;

    float acc[4][4];
#pragma unroll
    for (int i = 0; i < 4; i++)
#pragma unroll
        for (int j = 0; j < 4; j++) acc[i][j] = 0.f;

    for (int d0 = 0; d0 < WD; d0 += 32) {
#pragma unroll
        for (int i = tid; i < 64 * 32; i += 256) {
            int r = i >> 5, c = i & 31;
            int m = m0 + r;
            As[r][c] = (m < M_WE) ? we_in[m * WD + d0 + c] : 0.f;
            Bs[r][c] = Wfc[(k0 + r) * WD + d0 + c];
        }
        __syncthreads();
#pragma unroll
        for (int dd = 0; dd < 32; dd++) {
            float a[4], b[4];
#pragma unroll
            for (int i = 0; i < 4; i++) a[i] = As[ty * 4 + i][dd];
#pragma unroll
            for (int j = 0; j < 4; j++) b[j] = Bs[tx * 4 + j][dd];
#pragma unroll
            for (int i = 0; i < 4; i++)
#pragma unroll
                for (int j = 0; j < 4; j++) acc[i][j] += a[i] * b[j];
        }
        __syncthreads();
    }

#pragma unroll
    for (int i = 0; i < 4; i++) {
        int m = m0 + ty * 4 + i;
        if (m < M_WE) {
#pragma unroll
            for (int j = 0; j < 4; j++) {
                int k = k0 + tx * 4 + j;
                g_we[m * HW2 + k] = acc[i][j] + bfc[k];
            }
        }
    }
}

// ---------------------------------------------------------------------------
// Kernel 2: fused  scores -> softmax -> att_feat  per (batch, 64-channel tile)
//   Phase 1: scores[c][n] = sum_k f[b,c,k] * we[b,n,k]   (GEMM 64x80xK=1024)
//   Phase 2: softmax over n (77 valid) in smem
//   Phase 3: out[c][k]   = sum_n att[c][n] * we[b,n,k]    (GEMM 64x1024xK=77)
// ---------------------------------------------------------------------------
__global__ void attn_fused(const float* __restrict__ feat,
                           float* __restrict__ out) {
    // Union buffer: phase1 tiles (As 64x33 + Bs 80x33 = 4752 f) vs
    //               phase3 tile  (Ws 77x64 = 4928 f)
    __shared__ float U[4928];
    __shared__ float S[64 * 81];   // scores / attention weights, padded stride 81

    float* As = U;              // [64][33]
    float* Bs = U + 64 * 33;    // [80][33]
    float* Ws = U;              // [77][64]

    const int tid = threadIdx.x;
    const int tx  = tid & 15;
    const int ty  = tid >> 4;
    const int b   = blockIdx.y;
    const int c0  = blockIdx.x * 64;

    const float* fb  = feat + ((size_t)b * CC + c0) * HW2;
    const float* web = g_we + (size_t)b * NW * HW2;
    float*       ob  = out  + ((size_t)b * CC + c0) * HW2;

    // ---- Phase 1: scores (64 channels x 80 n, n>=77 padded with zeros) ----
    float acc[4][5];
#pragma unroll
    for (int i = 0; i < 4; i++)
#pragma unroll
        for (int j = 0; j < 5; j++) acc[i][j] = 0.f;

    for (int k0 = 0; k0 < HW2; k0 += 32) {
#pragma unroll
        for (int i = tid; i < 64 * 32; i += 256) {
            int r = i >> 5, c = i & 31;
            As[r * 33 + c] = fb[r * HW2 + k0 + c];
        }
#pragma unroll
        for (int i = tid; i < 80 * 32; i += 256) {
            int r = i >> 5, c = i & 31;
            Bs[r * 33 + c] = (r < NW) ? web[r * HW2 + k0 + c] : 0.f;
        }
        __syncthreads();
#pragma unroll
        for (int kk = 0; kk < 32; kk++) {
            float a[4], bn[5];
#pragma unroll
            for (int i = 0; i < 4; i++) a[i] = As[(ty * 4 + i) * 33 + kk];
#pragma unroll
            for (int j = 0; j < 5; j++) bn[j] = Bs[(tx * 5 + j) * 33 + kk];
#pragma unroll
            for (int i = 0; i < 4; i++)
#pragma unroll
                for (int j = 0; j < 5; j++) acc[i][j] += a[i] * bn[j];
        }
        __syncthreads();
    }

    // store scores to smem
#pragma unroll
    for (int i = 0; i < 4; i++)
#pragma unroll
        for (int j = 0; j < 5; j++)
            S[(ty * 4 + i) * 81 + (tx * 5 + j)] = acc[i][j];
    __syncthreads();

    // ---- Phase 2: softmax over n (77) per channel row ----
    if (tid < 64) {
        float* row = S + tid * 81;
        float mx = -1e30f;
        for (int n = 0; n < NW; n++) mx = fmaxf(mx, row[n]);
        float s = 0.f;
        for (int n = 0; n < NW; n++) {
            float e = __expf(row[n] - mx);
            row[n] = e;
            s += e;
        }
        float inv = 1.f / s;
        for (int n = 0; n < NW; n++) row[n] *= inv;
    }
    __syncthreads();

    // ---- Phase 3: att_feat: out[c][k] = sum_n att[c][n] * we[n][k] ----
    for (int kc = 0; kc < HW2; kc += 64) {
        // load we tile [77][64]
        for (int i = tid; i < NW * 64; i += 256) {
            int r = i >> 6, c = i & 63;
            Ws[i] = web[r * HW2 + kc + c];
        }
        __syncthreads();

        float4 acc2[4];
#pragma unroll
        for (int i = 0; i < 4; i++) acc2[i] = make_float4(0.f, 0.f, 0.f, 0.f);

        for (int n = 0; n < NW; n++) {
            float4 wv = *(const float4*)&Ws[n * 64 + tx * 4];
#pragma unroll
            for (int i = 0; i < 4; i++) {
                float a = S[(ty * 4 + i) * 81 + n];
                acc2[i].x += a * wv.x;
                acc2[i].y += a * wv.y;
                acc2[i].z += a * wv.z;
                acc2[i].w += a * wv.w;
            }
        }

#pragma unroll
        for (int i = 0; i < 4; i++) {
            *(float4*)&ob[(ty * 4 + i) * HW2 + kc + tx * 4] = acc2[i];
        }
        __syncthreads();
    }
}

// ---------------------------------------------------------------------------
extern "C" void kernel_launch(void* const* d_in, const int* in_sizes, int n_in,
                              void* d_out, int out_size) {
    const float* feat     = (const float*)d_in[0];   // 32*512*32*32
    const float* word_emb = (const float*)d_in[1];   // 32*77*256
    const float* W_fc     = (const float*)d_in[2];   // 1024*256
    const float* b_fc     = (const float*)d_in[3];   // 1024
    float* out            = (float*)d_out;           // 32*512*1024

    (void)in_sizes; (void)n_in; (void)out_size;

    // Kernel 1: we = word_emb @ W_fc^T + b_fc
    dim3 g1(HW2 / 64, (M_WE + 63) / 64);   // (16, 39)
    we_gemm<<<g1, 256>>>(word_emb, W_fc, b_fc);

    // Kernel 2: fused scores/softmax/att_feat
    dim3 g2(CC / 64, BB);                  // (8, 32)
    attn_fused<<<g2, 256>>>(feat, out);
}